// round 9
// baseline (speedup 1.0000x reference)
#include <cuda_runtime.h>

// Problem constants (fixed by the reference).
#define BB   64
#define TT   512
#define VV   96
#define HH   1024
#define NCTA 128   // 16 k-chunks x 8 column tiles, co-resident (1 CTA/SM, 48KB smem)

// ---------------------------------------------------------------------------
// Scratch (device globals: allocation-free per harness rules)
// ---------------------------------------------------------------------------
__device__ float g_xproj[(size_t)BB * TT * HH];     // x @ Wxh + bh, [b][t][h]
__device__ float g_hs   [(size_t)BB * TT * HH];     // hidden states, [b][t][h]
__device__ float g_partial[16 * BB * HH];           // split-K partials [kc][b][j], 4MB
__device__ unsigned g_cnt = 0;
__device__ volatile unsigned g_gen = 0;

// ---------------------------------------------------------------------------
// Global software barrier — EXACTLY the R3/R6/R8-proven version (incl. nanosleep).
// ---------------------------------------------------------------------------
__device__ __forceinline__ void gbar()
{
    __syncthreads();
    if (threadIdx.x == 0) {
        __threadfence();                      // release prior global stores
        unsigned g = g_gen;
        if (atomicAdd(&g_cnt, 1u) == NCTA - 1) {
            g_cnt = 0;
            __threadfence();
            g_gen = g + 1;
        } else {
            while (g_gen == g) { __nanosleep(64); }
        }
        __threadfence();                      // acquire
    }
    __syncthreads();
}

// ---------------------------------------------------------------------------
// Packed fp32x2 (Blackwell FFMA2). Two exact IEEE fp32 FMAs per instruction.
// ---------------------------------------------------------------------------
__device__ __forceinline__ unsigned long long splat2(float a)
{
    unsigned long long r;
    asm("mov.b64 %0, {%1, %1};" : "=l"(r) : "f"(a));
    return r;
}
__device__ __forceinline__ void ffma2(unsigned long long& d,
                                      unsigned long long a, unsigned long long b)
{
    asm("fma.rn.f32x2 %0, %1, %2, %0;" : "+l"(d) : "l"(a), "l"(b));
}

// ---------------------------------------------------------------------------
// Kernel 1: xproj[r][j] = sum_v x[r][v] * Wxh[v][j] + bh[j]   (unchanged, R3)
// ---------------------------------------------------------------------------
__global__ void __launch_bounds__(256) xproj_kernel(const float* __restrict__ x,
                                                    const float* __restrict__ Wxh,
                                                    const float* __restrict__ bh)
{
    __shared__ float sa[64][36];
    __shared__ float sw[32][64];

    const int tid = threadIdx.x;
    const int tx  = tid & 15;
    const int ty  = tid >> 4;
    const size_t row0 = (size_t)blockIdx.y * 64;
    const int jt  = blockIdx.x;

    float acc[4][4] = {};

    #pragma unroll 1
    for (int K0 = 0; K0 < 96; K0 += 32) {
        #pragma unroll
        for (int i = 0; i < 2; ++i) {
            int idx = tid + i * 256;
            int r = idx >> 3, k4 = (idx & 7) * 4;
            float4 v = *(const float4*)(x + (row0 + r) * 96 + K0 + k4);
            *(float4*)&sa[r][k4] = v;
        }
        #pragma unroll
        for (int i = 0; i < 2; ++i) {
            int idx = tid + i * 256;
            int kk = idx >> 4, j4 = (idx & 15) * 4;
            float4 v = *(const float4*)(Wxh + (size_t)(K0 + kk) * HH + jt * 64 + j4);
            *(float4*)&sw[kk][j4] = v;
        }
        __syncthreads();
        #pragma unroll 4
        for (int k = 0; k < 32; k += 4) {
            float ha[4][4], wa[4][4];
            #pragma unroll
            for (int i = 0; i < 4; ++i) {
                float4 v = *(const float4*)&sa[ty * 4 + i][k];
                ha[i][0] = v.x; ha[i][1] = v.y; ha[i][2] = v.z; ha[i][3] = v.w;
            }
            #pragma unroll
            for (int kk = 0; kk < 4; ++kk) {
                float4 v = *(const float4*)&sw[k + kk][tx * 4];
                wa[kk][0] = v.x; wa[kk][1] = v.y; wa[kk][2] = v.z; wa[kk][3] = v.w;
            }
            #pragma unroll
            for (int kk = 0; kk < 4; ++kk)
                #pragma unroll
                for (int i = 0; i < 4; ++i)
                    #pragma unroll
                    for (int j = 0; j < 4; ++j)
                        acc[i][j] += ha[i][kk] * wa[kk][j];
        }
        __syncthreads();
    }

    float4 bv = *(const float4*)(bh + jt * 64 + tx * 4);
    #pragma unroll
    for (int i = 0; i < 4; ++i) {
        float4 v = make_float4(acc[i][0] + bv.x, acc[i][1] + bv.y,
                               acc[i][2] + bv.z, acc[i][3] + bv.w);
        *(float4*)&g_xproj[(row0 + ty * 4 + i) * HH + jt * 64 + tx * 4] = v;
    }
}

// ---------------------------------------------------------------------------
// Kernel 2: persistent recurrence — FFMA2, 128 threads, 8x8 thread tile.
//   CTA bx: kc = bx>>3 (K chunk of 64), jt = bx&7 (128-col tile). Tile 64x128.
//   16 col-groups (tx) x 8 row-groups (ty); thread computes rows ty*8..+7,
//   cols tx*8..+7 as 4 packed f32x2 pairs. 1.0 B/FMA -> compute-bound 4096 cyc.
//   Phase 2: h_t = tanh(xproj + sum of 16 partials), 2 float2/thread.
//   Whh slice 64x128 (32KB) persistent; h tile 16KB swizzled. gbar unchanged.
// ---------------------------------------------------------------------------
__global__ void __launch_bounds__(128) rnn_kernel(const float* __restrict__ h0,
                                                  const float* __restrict__ Whh)
{
    __shared__ float sh[64][64];        // 16KB h tile [b][k], float4 cols XOR-(row&15)
    __shared__ float sw[64][128];       // 32KB Whh slice [k][j], persistent

    const int tid = threadIdx.x;
    const int bx  = blockIdx.x;
    const int kc  = bx >> 3;            // 0..15 (K chunk of 64)
    const int jt  = bx & 7;             // 0..7  (128-column tile)
    const int tx  = tid & 15;           // col group: cols tx*8..+7
    const int ty  = tid >> 4;           // row group: rows ty*8..+7

    // Preload Whh slice once: rows kc*64..+63, cols jt*128..+127. 2048 float4.
    #pragma unroll
    for (int i = 0; i < 16; ++i) {
        int idx = tid + i * 128;
        int kk = idx >> 5, j4 = (idx & 31) * 4;
        float4 v = *(const float4*)(Whh + (size_t)(kc * 64 + kk) * HH + jt * 128 + j4);
        *(float4*)&sw[kk][j4] = v;
    }
    __syncthreads();

    // Phase-2 output coordinates (2 float2 per thread, fixed).
    const int o2  = bx * 256 + tid * 2; // float2 index, 0..32766 even-paired
    const int p2b0 = o2 >> 9;           // both float2 of a thread share a row
    const int p2j0 = ((o2)     & 511) * 2;
    const int p2j1 = ((o2 + 1) & 511) * 2;

    for (int t = 0; t < TT; ++t) {
        const float* hb;
        size_t bstr;
        if (t == 0) { hb = h0;                          bstr = HH; }
        else        { hb = g_hs + (size_t)(t - 1) * HH; bstr = (size_t)TT * HH; }

        // ---- issue h-tile loads: 64 rows x 16 float4 = 1024 float4, 8/thread ----
        float4 ra[8];
        #pragma unroll
        for (int i = 0; i < 8; ++i) {
            int idx = tid + i * 128;
            int bb = idx >> 4, c = idx & 15;
            ra[i] = __ldcg((const float4*)(hb + (size_t)bb * bstr + kc * 64 + c * 4));
        }
        // ---- prefetch phase-2 xproj (independent, read-only) ----
        float2 xp0 = __ldcg((const float2*)(g_xproj + ((size_t)p2b0 * TT + t) * HH + p2j0));
        float2 xp1 = __ldcg((const float2*)(g_xproj + ((size_t)p2b0 * TT + t) * HH + p2j1));

        // ---- stage h tile (XOR swizzle, proven pattern) ----
        #pragma unroll
        for (int i = 0; i < 8; ++i) {
            int idx = tid + i * 128;
            int bb = idx >> 4, c = idx & 15;
            *(float4*)&sh[bb][((c ^ (bb & 15)) << 2)] = ra[i];
        }
        __syncthreads();

        // ---- compute: 8x8 tile, packed f32x2, K=64 ----
        unsigned long long acc[8][4] = {};   // [row][colpair] f32x2 (0 == {0,0})
        #pragma unroll 4
        for (int k = 0; k < 64; k += 4) {
            const int c4 = k >> 2;
            float4 a4[8];
            #pragma unroll
            for (int i = 0; i < 8; ++i) {
                int row = ty * 8 + i;
                a4[i] = *(const float4*)&sh[row][((c4 ^ (row & 15)) << 2)];  // broadcast
            }
            #pragma unroll
            for (int kk = 0; kk < 4; ++kk) {
                ulonglong2 w0 = *(const ulonglong2*)&sw[k + kk][tx * 8];      // cols tx*8..+3
                ulonglong2 w1 = *(const ulonglong2*)&sw[k + kk][tx * 8 + 4];  // cols tx*8+4..+7
                #pragma unroll
                for (int i = 0; i < 8; ++i) {
                    unsigned long long s = splat2(((const float*)&a4[i])[kk]);
                    ffma2(acc[i][0], s, w0.x);
                    ffma2(acc[i][1], s, w0.y);
                    ffma2(acc[i][2], s, w1.x);
                    ffma2(acc[i][3], s, w1.y);
                }
            }
        }
        __syncthreads();   // sh reusable next step only after all reads done

        // ---- publish split-K partials: rows ty*8..+7, cols jt*128+tx*8..+7 ----
        {
            float* pp = g_partial + (size_t)kc * (BB * HH) + jt * 128 + tx * 8;
            #pragma unroll
            for (int i = 0; i < 8; ++i) {
                int b = ty * 8 + i;
                *(ulonglong2*)&pp[(size_t)b << 10]       = make_ulonglong2(acc[i][0], acc[i][1]);
                *(ulonglong2*)&pp[((size_t)b << 10) + 4] = make_ulonglong2(acc[i][2], acc[i][3]);
            }
        }

        gbar();

        // ---- phase 2: reduce 16 partials + xproj, tanh, write h_t ----
        {
            float s0x = xp0.x, s0y = xp0.y, s1x = xp1.x, s1y = xp1.y;
            const float* pb0 = g_partial + (size_t)(p2b0 << 10) + p2j0;
            const float* pb1 = g_partial + (size_t)(p2b0 << 10) + p2j1;
            #pragma unroll
            for (int c = 0; c < 16; ++c) {
                float2 pv0 = __ldcg((const float2*)(pb0 + (size_t)c * (BB * HH)));
                float2 pv1 = __ldcg((const float2*)(pb1 + (size_t)c * (BB * HH)));
                s0x += pv0.x; s0y += pv0.y;
                s1x += pv1.x; s1y += pv1.y;
            }
            *(float2*)&g_hs[((size_t)p2b0 * TT + t) * HH + p2j0] = make_float2(tanhf(s0x), tanhf(s0y));
            *(float2*)&g_hs[((size_t)p2b0 * TT + t) * HH + p2j1] = make_float2(tanhf(s1x), tanhf(s1y));
        }

        gbar();
    }
}

// ---------------------------------------------------------------------------
// Kernel 3: logits[r][v] = sum_k hs[r][k] * Wl[v][k] + bl[v]  (unchanged, R3)
// ---------------------------------------------------------------------------
__global__ void __launch_bounds__(256) logits_kernel(const float* __restrict__ Wl,
                                                     const float* __restrict__ bl,
                                                     float* __restrict__ out)
{
    __shared__ float sa [64][36];
    __shared__ float swl[32][100];

    const int tid = threadIdx.x;
    const int tx  = tid & 15;
    const int ty  = tid >> 4;
    const size_t row0 = (size_t)blockIdx.x * 64;
    const int v0  = tx * 6;

    float acc[4][6] = {};

    #pragma unroll 1
    for (int K0 = 0; K0 < HH; K0 += 32) {
        #pragma unroll
        for (int i = 0; i < 2; ++i) {
            int idx = tid + i * 256;
            int r = idx >> 3, k4 = (idx & 7) * 4;
            float4 v = *(const float4*)(g_hs + (row0 + r) * HH + K0 + k4);
            *(float4*)&sa[r][k4] = v;
        }
        #pragma unroll
        for (int i = 0; i < 3; ++i) {
            int idx = tid + i * 256;
            int vv = idx >> 3, k4 = (idx & 7) * 4;
            float4 v = *(const float4*)(Wl + (size_t)vv * HH + K0 + k4);
            swl[k4 + 0][vv] = v.x;
            swl[k4 + 1][vv] = v.y;
            swl[k4 + 2][vv] = v.z;
            swl[k4 + 3][vv] = v.w;
        }
        __syncthreads();
        #pragma unroll 4
        for (int k = 0; k < 32; ++k) {
            float a0 = sa[ty * 4 + 0][k];
            float a1 = sa[ty * 4 + 1][k];
            float a2 = sa[ty * 4 + 2][k];
            float a3 = sa[ty * 4 + 3][k];
            #pragma unroll
            for (int j = 0; j < 6; ++j) {
                float w = swl[k][v0 + j];
                acc[0][j] += a0 * w;
                acc[1][j] += a1 * w;
                acc[2][j] += a2 * w;
                acc[3][j] += a3 * w;
            }
        }
        __syncthreads();
    }

    #pragma unroll
    for (int i = 0; i < 4; ++i)
        #pragma unroll
        for (int j = 0; j < 6; ++j)
            out[(row0 + ty * 4 + i) * VV + v0 + j] = acc[i][j] + bl[v0 + j];
}

// ---------------------------------------------------------------------------
// Kernel 4: h_last = hs[:, T-1, :]
// ---------------------------------------------------------------------------
__global__ void __launch_bounds__(256) hlast_kernel(float* __restrict__ out)
{
    int i = blockIdx.x * 256 + threadIdx.x;
    int b = i >> 10, j = i & 1023;
    out[i] = g_hs[((size_t)b * TT + (TT - 1)) * HH + j];
}

// ---------------------------------------------------------------------------
extern "C" void kernel_launch(void* const* d_in, const int* in_sizes, int n_in,
                              void* d_out, int out_size)
{
    const float* x   = (const float*)d_in[0];
    const float* h0  = (const float*)d_in[1];
    const float* Wxh = (const float*)d_in[2];
    const float* Whh = (const float*)d_in[3];
    const float* bh  = (const float*)d_in[4];
    const float* Wl  = (const float*)d_in[5];
    const float* bl  = (const float*)d_in[6];
    float* out = (float*)d_out;
    (void)in_sizes; (void)n_in;

    xproj_kernel <<<dim3(16, (BB * TT) / 64), 256>>>(x, Wxh, bh);
    rnn_kernel   <<<NCTA, 128>>>(h0, Whh);
    logits_kernel<<<(BB * TT) / 64, 256>>>(Wl, bl, out);

    const size_t logits_elems = (size_t)BB * TT * VV;
    if ((size_t)out_size >= logits_elems + (size_t)BB * HH)
        hlast_kernel<<<(BB * HH) / 256, 256>>>(out + logits_elems);
}

// round 10
// speedup vs baseline: 1.3919x; 1.3919x over previous
#include <cuda_runtime.h>

// Problem constants (fixed by the reference).
#define BB   64
#define TT   512
#define VV   96
#define HH   1024
#define NCTA 128   // 16 k-chunks x 8 column tiles, co-resident (1 CTA/SM, 48KB smem)

// ---------------------------------------------------------------------------
// Scratch (device globals: allocation-free per harness rules)
// ---------------------------------------------------------------------------
__device__ float g_xproj[(size_t)BB * TT * HH];     // x @ Wxh + bh, [b][t][h]
__device__ float g_hs   [(size_t)BB * TT * HH];     // hidden states, [b][t][h]
__device__ float g_partial[16 * BB * HH];           // split-K partials [kc][b][j], 4MB
__device__ unsigned g_bar = 0;                      // monotone grid-barrier counter

// Zero the barrier counter before each rnn run (graph replays reuse state).
__global__ void init_kernel() { if (threadIdx.x == 0) g_bar = 0; }

// ---------------------------------------------------------------------------
// Grid barrier, CG-style: monotone counter, release arrival (fire-and-forget
// REDG — no return-trip wait, release covers all prior stores via the
// preceding __syncthreads), acquire polling. No reset, no second variable:
// the last arrival IS the release.
// ---------------------------------------------------------------------------
__device__ __forceinline__ void gbar_wait(unsigned tgt)
{
    __syncthreads();
    if (threadIdx.x == 0) {
        asm volatile("red.release.gpu.global.add.u32 [%0], %1;"
                     :: "l"(&g_bar), "r"(1u) : "memory");
        unsigned v;
        while (true) {
            asm volatile("ld.acquire.gpu.global.u32 %0, [%1];"
                         : "=r"(v) : "l"(&g_bar) : "memory");
            if ((int)(v - tgt) >= 0) break;
            __nanosleep(32);
        }
    }
    __syncthreads();
}

// ---------------------------------------------------------------------------
// Packed fp32x2 (Blackwell FFMA2). Two exact IEEE fp32 FMAs per instruction.
// ---------------------------------------------------------------------------
__device__ __forceinline__ unsigned long long splat2(float a)
{
    unsigned long long r;
    asm("mov.b64 %0, {%1, %1};" : "=l"(r) : "f"(a));
    return r;
}
__device__ __forceinline__ void ffma2(unsigned long long& d,
                                      unsigned long long a, unsigned long long b)
{
    asm("fma.rn.f32x2 %0, %1, %2, %0;" : "+l"(d) : "l"(a), "l"(b));
}

// ---------------------------------------------------------------------------
// Kernel 1: xproj[r][j] = sum_v x[r][v] * Wxh[v][j] + bh[j]   (unchanged, R3)
// ---------------------------------------------------------------------------
__global__ void __launch_bounds__(256) xproj_kernel(const float* __restrict__ x,
                                                    const float* __restrict__ Wxh,
                                                    const float* __restrict__ bh)
{
    __shared__ float sa[64][36];
    __shared__ float sw[32][64];

    const int tid = threadIdx.x;
    const int tx  = tid & 15;
    const int ty  = tid >> 4;
    const size_t row0 = (size_t)blockIdx.y * 64;
    const int jt  = blockIdx.x;

    float acc[4][4] = {};

    #pragma unroll 1
    for (int K0 = 0; K0 < 96; K0 += 32) {
        #pragma unroll
        for (int i = 0; i < 2; ++i) {
            int idx = tid + i * 256;
            int r = idx >> 3, k4 = (idx & 7) * 4;
            float4 v = *(const float4*)(x + (row0 + r) * 96 + K0 + k4);
            *(float4*)&sa[r][k4] = v;
        }
        #pragma unroll
        for (int i = 0; i < 2; ++i) {
            int idx = tid + i * 256;
            int kk = idx >> 4, j4 = (idx & 15) * 4;
            float4 v = *(const float4*)(Wxh + (size_t)(K0 + kk) * HH + jt * 64 + j4);
            *(float4*)&sw[kk][j4] = v;
        }
        __syncthreads();
        #pragma unroll 4
        for (int k = 0; k < 32; k += 4) {
            float ha[4][4], wa[4][4];
            #pragma unroll
            for (int i = 0; i < 4; ++i) {
                float4 v = *(const float4*)&sa[ty * 4 + i][k];
                ha[i][0] = v.x; ha[i][1] = v.y; ha[i][2] = v.z; ha[i][3] = v.w;
            }
            #pragma unroll
            for (int kk = 0; kk < 4; ++kk) {
                float4 v = *(const float4*)&sw[k + kk][tx * 4];
                wa[kk][0] = v.x; wa[kk][1] = v.y; wa[kk][2] = v.z; wa[kk][3] = v.w;
            }
            #pragma unroll
            for (int kk = 0; kk < 4; ++kk)
                #pragma unroll
                for (int i = 0; i < 4; ++i)
                    #pragma unroll
                    for (int j = 0; j < 4; ++j)
                        acc[i][j] += ha[i][kk] * wa[kk][j];
        }
        __syncthreads();
    }

    float4 bv = *(const float4*)(bh + jt * 64 + tx * 4);
    #pragma unroll
    for (int i = 0; i < 4; ++i) {
        float4 v = make_float4(acc[i][0] + bv.x, acc[i][1] + bv.y,
                               acc[i][2] + bv.z, acc[i][3] + bv.w);
        *(float4*)&g_xproj[(row0 + ty * 4 + i) * HH + jt * 64 + tx * 4] = v;
    }
}

// ---------------------------------------------------------------------------
// Kernel 2: persistent recurrence — EXACTLY the R8 geometry/math (proven best:
// 256 threads, kc=16/jt=8, 64x128 tile, 4x8 FFMA2 thread tile). Only the
// grid-barrier implementation changed (gbar_wait above).
// ---------------------------------------------------------------------------
__global__ void __launch_bounds__(256) rnn_kernel(const float* __restrict__ h0,
                                                  const float* __restrict__ Whh)
{
    __shared__ float sh[64][64];        // 16KB h tile [b][k], float4 cols XOR-(row&15)
    __shared__ float sw[64][128];       // 32KB Whh slice [k][j], persistent

    const int tid = threadIdx.x;
    const int bx  = blockIdx.x;
    const int kc  = bx >> 3;            // 0..15 (K chunk of 64)
    const int jt  = bx & 7;             // 0..7  (128-column tile)
    const int tx  = tid & 15;           // col group: cols {tx*4..+3} and {64+tx*4..+3}
    const int ty  = tid >> 4;           // row group: rows ty*4..+3

    // Preload Whh slice once: rows kc*64..+63, cols jt*128..+127.
    #pragma unroll
    for (int i = 0; i < 8; ++i) {
        int idx = tid + i * 256;
        int kk = idx >> 5, j4 = (idx & 31) * 4;
        float4 v = *(const float4*)(Whh + (size_t)(kc * 64 + kk) * HH + jt * 128 + j4);
        *(float4*)&sw[kk][j4] = v;
    }
    __syncthreads();

    // Phase-2 output coordinates (1 float2 per thread, fixed; proven mapping).
    const int o2  = bx * 256 + tid;     // 0..32767
    const int p2b = o2 >> 9;            // batch row
    const int p2j = (o2 & 511) * 2;     // column (even)

    unsigned bar_tgt = NCTA;            // monotone barrier target

    for (int t = 0; t < TT; ++t) {
        const float* hb;
        size_t bstr;
        if (t == 0) { hb = h0;                          bstr = HH; }
        else        { hb = g_hs + (size_t)(t - 1) * HH; bstr = (size_t)TT * HH; }

        // ---- issue h-tile loads: 64 rows x 64 k = 1024 float4, 4/thread ----
        float4 ra[4];
        #pragma unroll
        for (int i = 0; i < 4; ++i) {
            int idx = tid + i * 256;
            int bb = idx >> 4, c = idx & 15;
            ra[i] = __ldcg((const float4*)(hb + (size_t)bb * bstr + kc * 64 + c * 4));
        }
        // ---- prefetch phase-2 xproj (independent, read-only) ----
        float2 xp = __ldcg((const float2*)(g_xproj + ((size_t)p2b * TT + t) * HH + p2j));

        // ---- stage h tile (XOR swizzle, proven pattern) ----
        #pragma unroll
        for (int i = 0; i < 4; ++i) {
            int idx = tid + i * 256;
            int bb = idx >> 4, c = idx & 15;
            *(float4*)&sh[bb][((c ^ (bb & 15)) << 2)] = ra[i];
        }
        __syncthreads();

        // ---- compute: 4 rows x 8 cols (two strided float4 groups), f32x2 ----
        unsigned long long acc[4][4] = {};
        #pragma unroll 4
        for (int k = 0; k < 64; k += 4) {
            const int c4 = k >> 2;
            float4 a4[4];
            #pragma unroll
            for (int i = 0; i < 4; ++i) {
                int row = ty * 4 + i;
                a4[i] = *(const float4*)&sh[row][((c4 ^ (row & 15)) << 2)];
            }
            #pragma unroll
            for (int kk = 0; kk < 4; ++kk) {
                ulonglong2 w0 = *(const ulonglong2*)&sw[k + kk][tx * 4];
                ulonglong2 w1 = *(const ulonglong2*)&sw[k + kk][64 + tx * 4];
                #pragma unroll
                for (int i = 0; i < 4; ++i) {
                    unsigned long long s = splat2(((const float*)&a4[i])[kk]);
                    ffma2(acc[i][0], s, w0.x);
                    ffma2(acc[i][1], s, w0.y);
                    ffma2(acc[i][2], s, w1.x);
                    ffma2(acc[i][3], s, w1.y);
                }
            }
        }
        __syncthreads();   // sh reusable next step only after all reads done

        // ---- publish split-K partials ----
        {
            float* pp = g_partial + (size_t)kc * (BB * HH) + jt * 128;
            #pragma unroll
            for (int i = 0; i < 4; ++i) {
                int b = ty * 4 + i;
                *(ulonglong2*)&pp[((size_t)b << 10) + tx * 4]      = make_ulonglong2(acc[i][0], acc[i][1]);
                *(ulonglong2*)&pp[((size_t)b << 10) + 64 + tx * 4] = make_ulonglong2(acc[i][2], acc[i][3]);
            }
        }

        gbar_wait(bar_tgt); bar_tgt += NCTA;

        // ---- phase 2: reduce 16 partials + xproj, tanh, write h_t ----
        {
            float sx = xp.x, sy = xp.y;
            const float* pb = g_partial + (size_t)(p2b << 10) + p2j;
            #pragma unroll
            for (int c = 0; c < 16; ++c) {
                float2 pv = __ldcg((const float2*)(pb + (size_t)c * (BB * HH)));
                sx += pv.x; sy += pv.y;
            }
            float2 o = make_float2(tanhf(sx), tanhf(sy));
            *(float2*)&g_hs[((size_t)p2b * TT + t) * HH + p2j] = o;
        }

        gbar_wait(bar_tgt); bar_tgt += NCTA;
    }
}

// ---------------------------------------------------------------------------
// Kernel 3: logits[r][v] = sum_k hs[r][k] * Wl[v][k] + bl[v]  (unchanged, R3)
// ---------------------------------------------------------------------------
__global__ void __launch_bounds__(256) logits_kernel(const float* __restrict__ Wl,
                                                     const float* __restrict__ bl,
                                                     float* __restrict__ out)
{
    __shared__ float sa [64][36];
    __shared__ float swl[32][100];

    const int tid = threadIdx.x;
    const int tx  = tid & 15;
    const int ty  = tid >> 4;
    const size_t row0 = (size_t)blockIdx.x * 64;
    const int v0  = tx * 6;

    float acc[4][6] = {};

    #pragma unroll 1
    for (int K0 = 0; K0 < HH; K0 += 32) {
        #pragma unroll
        for (int i = 0; i < 2; ++i) {
            int idx = tid + i * 256;
            int r = idx >> 3, k4 = (idx & 7) * 4;
            float4 v = *(const float4*)(g_hs + (row0 + r) * HH + K0 + k4);
            *(float4*)&sa[r][k4] = v;
        }
        #pragma unroll
        for (int i = 0; i < 3; ++i) {
            int idx = tid + i * 256;
            int vv = idx >> 3, k4 = (idx & 7) * 4;
            float4 v = *(const float4*)(Wl + (size_t)vv * HH + K0 + k4);
            swl[k4 + 0][vv] = v.x;
            swl[k4 + 1][vv] = v.y;
            swl[k4 + 2][vv] = v.z;
            swl[k4 + 3][vv] = v.w;
        }
        __syncthreads();
        #pragma unroll 4
        for (int k = 0; k < 32; ++k) {
            float a0 = sa[ty * 4 + 0][k];
            float a1 = sa[ty * 4 + 1][k];
            float a2 = sa[ty * 4 + 2][k];
            float a3 = sa[ty * 4 + 3][k];
            #pragma unroll
            for (int j = 0; j < 6; ++j) {
                float w = swl[k][v0 + j];
                acc[0][j] += a0 * w;
                acc[1][j] += a1 * w;
                acc[2][j] += a2 * w;
                acc[3][j] += a3 * w;
            }
        }
        __syncthreads();
    }

    #pragma unroll
    for (int i = 0; i < 4; ++i)
        #pragma unroll
        for (int j = 0; j < 6; ++j)
            out[(row0 + ty * 4 + i) * VV + v0 + j] = acc[i][j] + bl[v0 + j];
}

// ---------------------------------------------------------------------------
// Kernel 4: h_last = hs[:, T-1, :]
// ---------------------------------------------------------------------------
__global__ void __launch_bounds__(256) hlast_kernel(float* __restrict__ out)
{
    int i = blockIdx.x * 256 + threadIdx.x;
    int b = i >> 10, j = i & 1023;
    out[i] = g_hs[((size_t)b * TT + (TT - 1)) * HH + j];
}

// ---------------------------------------------------------------------------
extern "C" void kernel_launch(void* const* d_in, const int* in_sizes, int n_in,
                              void* d_out, int out_size)
{
    const float* x   = (const float*)d_in[0];
    const float* h0  = (const float*)d_in[1];
    const float* Wxh = (const float*)d_in[2];
    const float* Whh = (const float*)d_in[3];
    const float* bh  = (const float*)d_in[4];
    const float* Wl  = (const float*)d_in[5];
    const float* bl  = (const float*)d_in[6];
    float* out = (float*)d_out;
    (void)in_sizes; (void)n_in;

    init_kernel  <<<1, 32>>>();
    xproj_kernel <<<dim3(16, (BB * TT) / 64), 256>>>(x, Wxh, bh);
    rnn_kernel   <<<NCTA, 256>>>(h0, Whh);
    logits_kernel<<<(BB * TT) / 64, 256>>>(Wl, bl, out);

    const size_t logits_elems = (size_t)BB * TT * VV;
    if ((size_t)out_size >= logits_elems + (size_t)BB * HH)
        hlast_kernel<<<(BB * HH) / 256, 256>>>(out + logits_elems);
}

// round 11
// speedup vs baseline: 1.4347x; 1.0307x over previous
#include <cuda_runtime.h>

// Problem constants (fixed by the reference).
#define BB   64
#define TT   512
#define VV   96
#define HH   1024
#define NCTA 128   // 16 k-chunks x 8 column tiles, co-resident (1 CTA/SM, 48KB smem)

// ---------------------------------------------------------------------------
// Scratch (device globals: allocation-free per harness rules)
// ---------------------------------------------------------------------------
__device__ float g_xproj[(size_t)BB * TT * HH];     // x @ Wxh + bh, [b][t][h]
__device__ float g_hs   [(size_t)BB * TT * HH];     // hidden states, [b][t][h]
__device__ float g_partial[16 * BB * HH];           // split-K partials [kc][b][j], 4MB
__device__ unsigned g_bar = 0;                      // monotone grid-barrier counter

// Zero the barrier counter before each rnn run (graph replays reuse state).
__global__ void init_kernel() { if (threadIdx.x == 0) g_bar = 0; }

// ---------------------------------------------------------------------------
// Grid barrier (R10-proven): monotone counter, release arrival (fire-and-
// forget REDG), acquire polling. Last arrival IS the release.
// ---------------------------------------------------------------------------
__device__ __forceinline__ void gbar_wait(unsigned tgt)
{
    __syncthreads();
    if (threadIdx.x == 0) {
        asm volatile("red.release.gpu.global.add.u32 [%0], %1;"
                     :: "l"(&g_bar), "r"(1u) : "memory");
        unsigned v;
        while (true) {
            asm volatile("ld.acquire.gpu.global.u32 %0, [%1];"
                         : "=r"(v) : "l"(&g_bar) : "memory");
            if ((int)(v - tgt) >= 0) break;
            __nanosleep(32);
        }
    }
    __syncthreads();
}

// ---------------------------------------------------------------------------
// Packed fp32x2 (Blackwell FFMA2). Two exact IEEE fp32 FMAs per instruction.
// ---------------------------------------------------------------------------
__device__ __forceinline__ unsigned long long splat2(float a)
{
    unsigned long long r;
    asm("mov.b64 %0, {%1, %1};" : "=l"(r) : "f"(a));
    return r;
}
__device__ __forceinline__ void ffma2(unsigned long long& d,
                                      unsigned long long a, unsigned long long b)
{
    asm("fma.rn.f32x2 %0, %1, %2, %0;" : "+l"(d) : "l"(a), "l"(b));
}
__device__ __forceinline__ float2 unpack2(unsigned long long v)
{
    float2 f;
    asm("mov.b64 {%0, %1}, %2;" : "=f"(f.x), "=f"(f.y) : "l"(v));
    return f;
}

// ---------------------------------------------------------------------------
// Kernel 1: xproj[r][j] = sum_v x[r][v] * Wxh[v][j] + bh[j]
// R3 structure; inner product FFMA2-packed (per-column chains unchanged).
// ---------------------------------------------------------------------------
__global__ void __launch_bounds__(256) xproj_kernel(const float* __restrict__ x,
                                                    const float* __restrict__ Wxh,
                                                    const float* __restrict__ bh)
{
    __shared__ float sa[64][36];
    __shared__ float sw[32][64];

    const int tid = threadIdx.x;
    const int tx  = tid & 15;
    const int ty  = tid >> 4;
    const size_t row0 = (size_t)blockIdx.y * 64;
    const int jt  = blockIdx.x;

    unsigned long long acc[4][2] = {};   // [row][colpair] packed f32x2

    #pragma unroll 1
    for (int K0 = 0; K0 < 96; K0 += 32) {
        #pragma unroll
        for (int i = 0; i < 2; ++i) {
            int idx = tid + i * 256;
            int r = idx >> 3, k4 = (idx & 7) * 4;
            float4 v = *(const float4*)(x + (row0 + r) * 96 + K0 + k4);
            *(float4*)&sa[r][k4] = v;
        }
        #pragma unroll
        for (int i = 0; i < 2; ++i) {
            int idx = tid + i * 256;
            int kk = idx >> 4, j4 = (idx & 15) * 4;
            float4 v = *(const float4*)(Wxh + (size_t)(K0 + kk) * HH + jt * 64 + j4);
            *(float4*)&sw[kk][j4] = v;
        }
        __syncthreads();
        #pragma unroll 4
        for (int k = 0; k < 32; k += 4) {
            float4 a4[4];
            #pragma unroll
            for (int i = 0; i < 4; ++i)
                a4[i] = *(const float4*)&sa[ty * 4 + i][k];
            #pragma unroll
            for (int kk = 0; kk < 4; ++kk) {
                ulonglong2 w = *(const ulonglong2*)&sw[k + kk][tx * 4];
                #pragma unroll
                for (int i = 0; i < 4; ++i) {
                    unsigned long long s = splat2(((const float*)&a4[i])[kk]);
                    ffma2(acc[i][0], s, w.x);
                    ffma2(acc[i][1], s, w.y);
                }
            }
        }
        __syncthreads();
    }

    float4 bv = *(const float4*)(bh + jt * 64 + tx * 4);
    #pragma unroll
    for (int i = 0; i < 4; ++i) {
        float2 p0 = unpack2(acc[i][0]);
        float2 p1 = unpack2(acc[i][1]);
        float4 v = make_float4(p0.x + bv.x, p0.y + bv.y, p1.x + bv.z, p1.y + bv.w);
        *(float4*)&g_xproj[(row0 + ty * 4 + i) * HH + jt * 64 + tx * 4] = v;
    }
}

// ---------------------------------------------------------------------------
// Kernel 2: persistent recurrence — EXACTLY R10 (proven best) minus one
// provably redundant __syncthreads (gbar_wait opens with one; publish
// touches no smem; sh is not rewritten until after the barrier returns).
// ---------------------------------------------------------------------------
__global__ void __launch_bounds__(256) rnn_kernel(const float* __restrict__ h0,
                                                  const float* __restrict__ Whh)
{
    __shared__ float sh[64][64];        // 16KB h tile [b][k], float4 cols XOR-(row&15)
    __shared__ float sw[64][128];       // 32KB Whh slice [k][j], persistent

    const int tid = threadIdx.x;
    const int bx  = blockIdx.x;
    const int kc  = bx >> 3;            // 0..15 (K chunk of 64)
    const int jt  = bx & 7;             // 0..7  (128-column tile)
    const int tx  = tid & 15;
    const int ty  = tid >> 4;

    #pragma unroll
    for (int i = 0; i < 8; ++i) {
        int idx = tid + i * 256;
        int kk = idx >> 5, j4 = (idx & 31) * 4;
        float4 v = *(const float4*)(Whh + (size_t)(kc * 64 + kk) * HH + jt * 128 + j4);
        *(float4*)&sw[kk][j4] = v;
    }
    __syncthreads();

    const int o2  = bx * 256 + tid;     // 0..32767
    const int p2b = o2 >> 9;
    const int p2j = (o2 & 511) * 2;

    unsigned bar_tgt = NCTA;

    for (int t = 0; t < TT; ++t) {
        const float* hb;
        size_t bstr;
        if (t == 0) { hb = h0;                          bstr = HH; }
        else        { hb = g_hs + (size_t)(t - 1) * HH; bstr = (size_t)TT * HH; }

        float4 ra[4];
        #pragma unroll
        for (int i = 0; i < 4; ++i) {
            int idx = tid + i * 256;
            int bb = idx >> 4, c = idx & 15;
            ra[i] = __ldcg((const float4*)(hb + (size_t)bb * bstr + kc * 64 + c * 4));
        }
        float2 xp = __ldcg((const float2*)(g_xproj + ((size_t)p2b * TT + t) * HH + p2j));

        #pragma unroll
        for (int i = 0; i < 4; ++i) {
            int idx = tid + i * 256;
            int bb = idx >> 4, c = idx & 15;
            *(float4*)&sh[bb][((c ^ (bb & 15)) << 2)] = ra[i];
        }
        __syncthreads();

        unsigned long long acc[4][4] = {};
        #pragma unroll 4
        for (int k = 0; k < 64; k += 4) {
            const int c4 = k >> 2;
            float4 a4[4];
            #pragma unroll
            for (int i = 0; i < 4; ++i) {
                int row = ty * 4 + i;
                a4[i] = *(const float4*)&sh[row][((c4 ^ (row & 15)) << 2)];
            }
            #pragma unroll
            for (int kk = 0; kk < 4; ++kk) {
                ulonglong2 w0 = *(const ulonglong2*)&sw[k + kk][tx * 4];
                ulonglong2 w1 = *(const ulonglong2*)&sw[k + kk][64 + tx * 4];
                #pragma unroll
                for (int i = 0; i < 4; ++i) {
                    unsigned long long s = splat2(((const float*)&a4[i])[kk]);
                    ffma2(acc[i][0], s, w0.x);
                    ffma2(acc[i][1], s, w0.y);
                    ffma2(acc[i][2], s, w1.x);
                    ffma2(acc[i][3], s, w1.y);
                }
            }
        }
        // (standalone __syncthreads removed: gbar_wait below provides it;
        //  publish touches only global memory.)

        {
            float* pp = g_partial + (size_t)kc * (BB * HH) + jt * 128;
            #pragma unroll
            for (int i = 0; i < 4; ++i) {
                int b = ty * 4 + i;
                *(ulonglong2*)&pp[((size_t)b << 10) + tx * 4]      = make_ulonglong2(acc[i][0], acc[i][1]);
                *(ulonglong2*)&pp[((size_t)b << 10) + 64 + tx * 4] = make_ulonglong2(acc[i][2], acc[i][3]);
            }
        }

        gbar_wait(bar_tgt); bar_tgt += NCTA;

        {
            float sx = xp.x, sy = xp.y;
            const float* pb = g_partial + (size_t)(p2b << 10) + p2j;
            #pragma unroll
            for (int c = 0; c < 16; ++c) {
                float2 pv = __ldcg((const float2*)(pb + (size_t)c * (BB * HH)));
                sx += pv.x; sy += pv.y;
            }
            float2 o = make_float2(tanhf(sx), tanhf(sy));
            *(float2*)&g_hs[((size_t)p2b * TT + t) * HH + p2j] = o;
        }

        gbar_wait(bar_tgt); bar_tgt += NCTA;
    }
}

// ---------------------------------------------------------------------------
// Kernel 3: logits[r][v] = sum_k hs[r][k] * Wl[v][k] + bl[v]
// R3 structure; inner product FFMA2-packed (per-column chains unchanged).
// ---------------------------------------------------------------------------
__global__ void __launch_bounds__(256) logits_kernel(const float* __restrict__ Wl,
                                                     const float* __restrict__ bl,
                                                     float* __restrict__ out)
{
    __shared__ float sa [64][36];
    __shared__ float swl[32][100];

    const int tid = threadIdx.x;
    const int tx  = tid & 15;
    const int ty  = tid >> 4;
    const size_t row0 = (size_t)blockIdx.x * 64;
    const int v0  = tx * 6;

    unsigned long long acc[4][3] = {};   // [row][colpair] packed f32x2

    #pragma unroll 1
    for (int K0 = 0; K0 < HH; K0 += 32) {
        #pragma unroll
        for (int i = 0; i < 2; ++i) {
            int idx = tid + i * 256;
            int r = idx >> 3, k4 = (idx & 7) * 4;
            float4 v = *(const float4*)(g_hs + (row0 + r) * HH + K0 + k4);
            *(float4*)&sa[r][k4] = v;
        }
        #pragma unroll
        for (int i = 0; i < 3; ++i) {
            int idx = tid + i * 256;
            int vv = idx >> 3, k4 = (idx & 7) * 4;
            float4 v = *(const float4*)(Wl + (size_t)vv * HH + K0 + k4);
            swl[k4 + 0][vv] = v.x;
            swl[k4 + 1][vv] = v.y;
            swl[k4 + 2][vv] = v.z;
            swl[k4 + 3][vv] = v.w;
        }
        __syncthreads();
        #pragma unroll 4
        for (int k = 0; k < 32; ++k) {
            // w pairs: &swl[k][v0] is 8-byte aligned (row stride 400B, v0*4 = tx*24B)
            const unsigned long long* wp = (const unsigned long long*)&swl[k][v0];
            unsigned long long w0 = wp[0], w1 = wp[1], w2 = wp[2];
            #pragma unroll
            for (int i = 0; i < 4; ++i) {
                unsigned long long s = splat2(sa[ty * 4 + i][k]);
                ffma2(acc[i][0], s, w0);
                ffma2(acc[i][1], s, w1);
                ffma2(acc[i][2], s, w2);
            }
        }
        __syncthreads();
    }

    #pragma unroll
    for (int i = 0; i < 4; ++i) {
        float* orow = out + (row0 + ty * 4 + i) * VV + v0;
        #pragma unroll
        for (int p = 0; p < 3; ++p) {
            float2 v = unpack2(acc[i][p]);
            orow[p * 2 + 0] = v.x + bl[v0 + p * 2 + 0];
            orow[p * 2 + 1] = v.y + bl[v0 + p * 2 + 1];
        }
    }
}

// ---------------------------------------------------------------------------
// Kernel 4: h_last = hs[:, T-1, :]
// ---------------------------------------------------------------------------
__global__ void __launch_bounds__(256) hlast_kernel(float* __restrict__ out)
{
    int i = blockIdx.x * 256 + threadIdx.x;
    int b = i >> 10, j = i & 1023;
    out[i] = g_hs[((size_t)b * TT + (TT - 1)) * HH + j];
}

// ---------------------------------------------------------------------------
extern "C" void kernel_launch(void* const* d_in, const int* in_sizes, int n_in,
                              void* d_out, int out_size)
{
    const float* x   = (const float*)d_in[0];
    const float* h0  = (const float*)d_in[1];
    const float* Wxh = (const float*)d_in[2];
    const float* Whh = (const float*)d_in[3];
    const float* bh  = (const float*)d_in[4];
    const float* Wl  = (const float*)d_in[5];
    const float* bl  = (const float*)d_in[6];
    float* out = (float*)d_out;
    (void)in_sizes; (void)n_in;

    init_kernel  <<<1, 32>>>();
    xproj_kernel <<<dim3(16, (BB * TT) / 64), 256>>>(x, Wxh, bh);
    rnn_kernel   <<<NCTA, 256>>>(h0, Whh);
    logits_kernel<<<(BB * TT) / 64, 256>>>(Wl, bl, out);

    const size_t logits_elems = (size_t)BB * TT * VV;
    if ((size_t)out_size >= logits_elems + (size_t)BB * HH)
        hlast_kernel<<<(BB * HH) / 256, 256>>>(out + logits_elems);
}